// round 14
// baseline (speedup 1.0000x reference)
#include <cuda_runtime.h>
#include <math.h>

// CTC forward loss, T=512, N=32, C=8000, S=40 (Se = 2S+1 = 81).
//
// LINEAR-domain scaled forward algorithm (see R12). One warp per batch
// element, 3 consecutive states per lane (lanes 0-26 real; 27-31 dead).
//   a'[s] = (a[s] + a[s-1] + skip(s)*a[s-2]) * p[t, class(s)]
// p = ex2(lp*INV_LN2 + boost), boost = +13 live / -1e30 dead.
// Exact power-of-two warp renorm every 8 steps (butterfly spread 1 stage/step).
//
// This round: ZERO runtime branches in the recurrence. Main loop = 62 blocks
// of 8 steps whose ring reloads are provably in-bounds (no guard), addressed
// as LDG [P + j*STRIDE] with compile-time immediates; P bumped once per block.
// Tail = 1 renorm block (reloads t=505..511 only, compile-time) + 7 plain
// steps. The floating-point op sequence is bit-identical to the R12 kernel.

#define TT 512
#define NB 32
#define CC 8000
#define SS 40
#define SE 81
#define PF 8
#define STRIDE (NB * CC)

#define BOOST    13.0f
#define NEGBIG   (-1.0e30f)
#define INV_LN2  1.44269504088896341f
#define LN2      0.69314718055994531f

__device__ __forceinline__ float ex2f_(float x) {
    float y; asm("ex2.approx.ftz.f32 %0, %1;" : "=f"(y) : "f"(x)); return y;
}
__device__ __forceinline__ float lg2f_(float x) {
    float y; asm("lg2.approx.ftz.f32 %0, %1;" : "=f"(y) : "f"(x)); return y;
}

// Core recurrence on ring slot jslot (compile-time constant).
#define STEP_CORE(jslot) do {                                                  \
    const float l0 = ex2f_(__fmaf_rn(r0[jslot], INV_LN2, bst0));               \
    const float l1 = ex2f_(__fmaf_rn(r1[jslot], INV_LN2, bst1));               \
    const float l2 = ex2f_(__fmaf_rn(r2[jslot], INV_LN2, bst2));               \
    float p1v = __shfl_up_sync(0xffffffffu, a1, 1);                            \
    float p2v = __shfl_up_sync(0xffffffffu, a2, 1);                            \
    p1v = (lane == 0) ? 0.0f : p1v;                                            \
    p2v = (lane == 0) ? 0.0f : p2v;                                            \
    const float n0 = __fmaf_rn(sk0, p1v, a0 + p2v) * l0;                       \
    const float n1 = __fmaf_rn(sk1, p2v, a1 + a0)  * l1;                       \
    const float n2 = __fmaf_rn(sk2, a0,  a2 + a1)  * l2;                       \
    a0 = n0; a1 = n1; a2 = n2;                                                 \
} while (0)

// Step with unconditional ring reload (compile-time immediate offsets).
#define STEP_R(jslot) do {                                                     \
    const float t0 = __ldg(P0 + (jslot) * STRIDE);                             \
    const float t1 = __ldg(P1 + (jslot) * STRIDE);                             \
    const float t2 = __ldg(P2 + (jslot) * STRIDE);                             \
    STEP_CORE(jslot);                                                          \
    r0[jslot] = t0; r1[jslot] = t1; r2[jslot] = t2;                            \
} while (0)

// Step without reload.
#define STEP_N(jslot) STEP_CORE(jslot)

__global__ __launch_bounds__(32, 1)
void ctc_lin_kernel(const float* __restrict__ lp,      // (T, N, C)
                    const int*   __restrict__ targets, // (N, S)
                    const int*   __restrict__ tgt_len, // (N,)
                    float*       __restrict__ out)     // (N,)
{
    const int n    = blockIdx.x;
    const int lane = threadIdx.x;
    const int sb   = (lane <= 26) ? 3 * lane : (SE - 3);   // lanes 27-31 dead
    const int Ln   = tgt_len[n];
    const int smax = 2 * Ln;                               // highest live state

    const int* tg = targets + n * SS;
    int   cls[3];
    float skf[3], bst[3];
#pragma unroll
    for (int k = 0; k < 3; ++k) {
        const int s = sb + k;
        if (s & 1) {
            cls[k] = tg[s >> 1];
            skf[k] = (s >= 3 && cls[k] != tg[(s - 3) >> 1]) ? 1.0f : 0.0f;
        } else {
            cls[k] = 0;
            skf[k] = 0.0f;
        }
        bst[k] = (lane <= 26 && s <= smax) ? BOOST : NEGBIG;
    }
    const float sk0 = skf[0], sk1 = skf[1], sk2 = skf[2];
    const float bst0 = bst[0], bst1 = bst[1], bst2 = bst[2];

    const float* q0 = lp + (unsigned)n * CC + (unsigned)cls[0];
    const float* q1 = lp + (unsigned)n * CC + (unsigned)cls[1];
    const float* q2 = lp + (unsigned)n * CC + (unsigned)cls[2];

    // t = 0 init (boosted linear domain).
    float a0 = 0.0f, a1 = 0.0f, a2 = 0.0f;
    if (sb == 0) {
        a0 = ex2f_(__fmaf_rn(__ldg(q0), INV_LN2, BOOST));
        a1 = ex2f_(__fmaf_rn(__ldg(q1), INV_LN2, BOOST));
    }

    // Prefetch ring for t = 1..8 (slot j <-> t = tb + j with tb = 1).
    float r0[PF], r1[PF], r2[PF];
#pragma unroll
    for (int j = 0; j < PF; ++j) {
        const unsigned off = (unsigned)(j + 1) * (unsigned)STRIDE;
        r0[j] = __ldg(q0 + off);
        r1[j] = __ldg(q1 + off);
        r2[j] = __ldg(q2 + off);
    }

    // Reload pointers: at block tb, slot j reloads t = tb + 8 + j, i.e.
    // Pk + j*STRIDE with Pk = qk + (tb+8)*STRIDE. Initialize for tb = 1.
    const float* P0 = q0 + (size_t)9 * STRIDE;
    const float* P1 = q1 + (size_t)9 * STRIDE;
    const float* P2 = q2 + (size_t)9 * STRIDE;

    int lcr = 0;   // accumulated renorm log2 (warp-uniform)

    // Main loop: 62 blocks, t = 1..496; reloads t = 9..504 (always legal).
    // Renorm butterfly identical in structure/timing to the R12 kernel.
#pragma unroll 1
    for (int blk = 0; blk < 62; ++blk) {
        float m;
        STEP_R(0); m = fmaxf(fmaxf(a0, a1), a2);
        STEP_R(1); m = fmaxf(m, __shfl_xor_sync(0xffffffffu, m, 1));
        STEP_R(2); m = fmaxf(m, __shfl_xor_sync(0xffffffffu, m, 2));
        STEP_R(3); m = fmaxf(m, __shfl_xor_sync(0xffffffffu, m, 4));
        STEP_R(4); m = fmaxf(m, __shfl_xor_sync(0xffffffffu, m, 8));
        STEP_R(5); m = fmaxf(m, __shfl_xor_sync(0xffffffffu, m, 16));
        int g; float sc;
        STEP_R(6);
        {
            const int E = (__float_as_int(m) >> 23) & 255;  // m > 0 (live)
            g  = 127 - E;                                   // scale = 2^g exact
            sc = __int_as_float((127 + g) << 23);
        }
        STEP_R(7);
        a0 *= sc; a1 *= sc; a2 *= sc;
        lcr += g;
        P0 += 8 * STRIDE; P1 += 8 * STRIDE; P2 += 8 * STRIDE;
    }

    // Tail renorm block: t = 497..504; reloads t = 505..511 (j = 0..6 only).
    {
        float m;
        STEP_R(0); m = fmaxf(fmaxf(a0, a1), a2);
        STEP_R(1); m = fmaxf(m, __shfl_xor_sync(0xffffffffu, m, 1));
        STEP_R(2); m = fmaxf(m, __shfl_xor_sync(0xffffffffu, m, 2));
        STEP_R(3); m = fmaxf(m, __shfl_xor_sync(0xffffffffu, m, 4));
        STEP_R(4); m = fmaxf(m, __shfl_xor_sync(0xffffffffu, m, 8));
        STEP_R(5); m = fmaxf(m, __shfl_xor_sync(0xffffffffu, m, 16));
        int g; float sc;
        STEP_R(6);
        {
            const int E = (__float_as_int(m) >> 23) & 255;
            g  = 127 - E;
            sc = __int_as_float((127 + g) << 23);
        }
        STEP_N(7);
        a0 *= sc; a1 *= sc; a2 *= sc;
        lcr += g;
    }

    // Final 7 steps: t = 505..511 (slots 0..6), no reloads.
    STEP_N(0); STEP_N(1); STEP_N(2); STEP_N(3);
    STEP_N(4); STEP_N(5); STEP_N(6);

    // Publish final alphas from owner lanes (0..26).
    __shared__ float fin[SE];
    if (lane <= 26) { fin[sb] = a0; fin[sb + 1] = a1; fin[sb + 2] = a2; }
    __syncwarp();

    if (lane == 0) {
        const int   len  = 2 * Ln + 1;
        const float ssum = fin[len - 1] + fin[len - 2];
        int e2; const float mant = frexpf(ssum, &e2);
        const float log2a = lg2f_(mant) + (float)e2;
        const float logP_ln = (log2a - (float)lcr - BOOST * 512.0f) * LN2;
        out[n] = -logP_ln / (float)Ln;
    }
}

extern "C" void kernel_launch(void* const* d_in, const int* in_sizes, int n_in,
                              void* d_out, int out_size) {
    const float* lp      = (const float*)d_in[0];  // log_probs (T, N, C)
    const int*   targets = (const int*)  d_in[1];  // (N, S)
    // d_in[2] = input_lengths — reference ignores them (always full T)
    const int*   tlen    = (const int*)  d_in[3];  // (N,)
    ctc_lin_kernel<<<NB, 32>>>(lp, targets, tlen, (float*)d_out);
}